// round 6
// baseline (speedup 1.0000x reference)
#include <cuda_runtime.h>
#include <math_constants.h>

#define B_    32
#define N_    128
#define C_    25
#define NC    3200                      // N_*C_ candidates per center
#define S_    13107200                  // B_*N_*N_*C_ elements per output tensor
#define RAD2  64.0f
#define EPS2  1e-4f
#define NT    256
#define NBIN  256
#define CAP   128
#define PREF  8.0f                      // prefilter bound for fine histogram

__global__ void zero_counts_kernel(float* __restrict__ out) {
    if (threadIdx.x < B_) out[(size_t)3 * S_ + threadIdx.x] = 0.0f;
}

__global__ __launch_bounds__(NT, 6)
void pbc_graph_kernel(const float* __restrict__ pos,
                      const float* __restrict__ cell,
                      float* __restrict__ out) {
    const int pair = blockIdx.x;        // 2048 blocks, 2 centers each
    const int b  = pair >> 6;
    const int i0 = (pair & 63) * 2;
    const int tid = threadIdx.x;

    __shared__ float4 spos4[N_];
    __shared__ float4 soff[C_];
    __shared__ __align__(16) float sdist[2][NC];
    __shared__ float  sctf[C_];
    __shared__ int    hist[2][NBIN];
    __shared__ int    s_n[2], s_t[2], s_cntlo[2], s_total[2];
    __shared__ unsigned long long slist[2][CAP];
    __shared__ float  s_Tf[2];
    __shared__ int    s_Tc[2];

    // ---- setup ----
    if (tid < N_) {
        const float* p = pos + (size_t)b * N_ * 3 + tid * 3;
        spos4[tid] = make_float4(p[0], p[1], p[2], 0.0f);
    }
    if (tid >= N_ && tid < N_ + C_) {
        int c = tid - N_;
        float u0 = (float)(c / 5 - 2);
        float u1 = (float)(c % 5 - 2);
        const float* cb = cell + b * 9;
        soff[c] = make_float4(
            __fmaf_rn(u0, cb[0], __fmul_rn(u1, cb[3])),
            __fmaf_rn(u0, cb[1], __fmul_rn(u1, cb[4])),
            __fmaf_rn(u0, cb[2], __fmul_rn(u1, cb[5])), 0.0f);
        sctf[c] = (float)(5 * (c / 5 + c % 5));
    }
    ((int*)hist)[tid] = 0;
    ((int*)hist)[tid + NT] = 0;
    if (tid == 0) {
        s_n[0] = s_n[1] = 0;
        s_t[0] = s_t[1] = -1;
        s_cntlo[0] = s_cntlo[1] = 0;
    }
    __syncthreads();

    // ---- phase 1: thread = (j, half); both centers; fine histogram d2<8 ----
    const int j    = tid >> 1;
    const int half = tid & 1;
    const int jbase = j * 25;
    const float4 rj = spos4[j];

#pragma unroll
    for (int u = 0; u < 2; u++) {
        const float4 pi = spos4[i0 + u];
        const float rx = __fsub_rn(rj.x, pi.x);
        const float ry = __fsub_rn(rj.y, pi.y);
        const float rz = __fsub_rn(rj.z, pi.z);
        float* sd = sdist[u];
        int*   hh = hist[u];
        if (half == 0) {
#pragma unroll
            for (int c = 0; c < 13; c++) {
                float4 o = soff[c];
                float dx = __fadd_rn(rx, o.x);
                float dy = __fadd_rn(ry, o.y);
                float dz = __fadd_rn(rz, o.z);
                float d2 = __fmaf_rn(dx, dx, __fmaf_rn(dy, dy, __fmul_rn(dz, dz)));
                bool within = (d2 <= RAD2) && (d2 > EPS2);
                sd[jbase + c] = within ? d2 : CUDART_INF_F;
                if (within && d2 < PREF) atomicAdd(&hh[(int)(d2 * 32.0f)], 1);
            }
        } else {
#pragma unroll
            for (int c = 13; c < 25; c++) {
                float4 o = soff[c];
                float dx = __fadd_rn(rx, o.x);
                float dy = __fadd_rn(ry, o.y);
                float dz = __fadd_rn(rz, o.z);
                float d2 = __fmaf_rn(dx, dx, __fmaf_rn(dy, dy, __fmul_rn(dz, dz)));
                bool within = (d2 <= RAD2) && (d2 > EPS2);
                sd[jbase + c] = within ? d2 : CUDART_INF_F;
                if (within && d2 < PREF) atomicAdd(&hh[(int)(d2 * 32.0f)], 1);
            }
        }
    }

    // ---- phase 2: parallel scans (warps 0/1); rare full-range fallback ----
    float scaleL[2] = {32.0f, 32.0f};
    float boundL[2] = {PREF, PREF};
    bool  fell[2]   = {false, false};
    for (int pass = 0; ; pass++) {
        __syncthreads();                        // hist ready
        if (tid < 64) {
            const int u = tid >> 5, lane = tid & 31;
            int loc[8], sum = 0;
#pragma unroll
            for (int k = 0; k < 8; k++) { loc[k] = hist[u][lane * 8 + k]; sum += loc[k]; }
            int pre = sum;
#pragma unroll
            for (int d = 1; d < 32; d <<= 1) {
                int v = __shfl_up_sync(0xffffffffu, pre, d);
                if (lane >= d) pre += v;
            }
            int total = __shfl_sync(0xffffffffu, pre, 31);
            pre -= sum;
            if (lane == 0) s_total[u] = total;
            if (total > 32 && pre < 32 && 32 <= pre + sum) {
                int cum = pre;
#pragma unroll
                for (int k = 0; k < 8; k++) {
                    if (cum < 32 && cum + loc[k] >= 32) { s_t[u] = lane * 8 + k; s_cntlo[u] = cum; }
                    cum += loc[k];
                }
            }
        }
        __syncthreads();
        const bool fb0 = (s_total[0] < 32) && !fell[0];
        const bool fb1 = (s_total[1] < 32) && !fell[1];
        if ((!fb0 && !fb1) || pass == 1) break;
        if (fb0) { ((int*)hist)[tid] = 0; }
        if (fb1) { ((int*)hist)[tid + NT] = 0; }
        __syncthreads();
#pragma unroll
        for (int u = 0; u < 2; u++) {
            if (!(u == 0 ? fb0 : fb1)) continue;
            scaleL[u] = 4.0f; boundL[u] = CUDART_INF_F; fell[u] = true;
            const int cb = half ? 13 : 0, ce = half ? 25 : 13;
            for (int c = cb; c < ce; c++) {
                float d = sdist[u][jbase + c];
                if (d <= RAD2)
                    atomicAdd(&hist[u][min((int)(d * 4.0f), NBIN - 1)], 1);
            }
        }
    }

    // ---- compact boundary bins + exact rank (stable (d2, cand) key) ----
#pragma unroll
    for (int u = 0; u < 2; u++) {
        if (s_total[u] > 32) {
            const int tbin = s_t[u];
            const float bnd = boundL[u], scl = scaleL[u];
            const int cb = half ? 13 : 0, ce = half ? 25 : 13;
            for (int c = cb; c < ce; c++) {
                float d = sdist[u][jbase + c];
                if (d < bnd && min((int)(d * scl), NBIN - 1) == tbin) {
                    int p = atomicAdd(&s_n[u], 1);
                    if (p < CAP)
                        slist[u][p] = ((unsigned long long)__float_as_uint(d) << 12)
                                    | (unsigned)(jbase + c);
                }
            }
        }
    }
    __syncthreads();
#pragma unroll
    for (int u = 0; u < 2; u++) {
        if (s_total[u] > 32) {
            int n = min(s_n[u], CAP);
            int need = 32 - s_cntlo[u];
            if (tid < n) {
                unsigned long long k = slist[u][tid];
                int r = 0;
                for (int m = 0; m < n; m++) r += (slist[u][m] < k) ? 1 : 0;
                if (r == need - 1) {
                    s_Tf[u] = __uint_as_float((unsigned)(k >> 12));
                    s_Tc[u] = (int)(k & 0xFFFu);
                }
            }
        } else if (tid == 0) {
            s_Tf[u] = boundL[u];        // keep all hist-covered (strict <)
            s_Tc[u] = -1;
        }
    }
    __syncthreads();

    // ---- phase 3: bulk writes with strict d < Tf (ties fixed up after) ----
#pragma unroll
    for (int u = 0; u < 2; u++) {
        const float Tf = s_Tf[u];
        const float4* sd4 = (const float4*)sdist[u];
        const size_t center = (size_t)(b * N_ + i0 + u);
        float4* o0 = (float4*)out                    + (center * NC >> 2);
        float4* o1 = (float4*)(out + (size_t)S_)     + (center * NC >> 2);
        float4* o2 = (float4*)(out + (size_t)2 * S_) + (center * NC >> 2);
        for (int v = tid; v < NC / 4; v += NT) {
            float4 dv = sd4[v];
            bool k0 = dv.x < Tf, k1 = dv.y < Tf, k2 = dv.z < Tf, k3 = dv.w < Tf;
            float4 od = make_float4(0.f, 0.f, 0.f, 0.f);
            float4 oc = make_float4(0.f, 0.f, 0.f, 0.f);
            float4 om = make_float4(0.f, 0.f, 0.f, 0.f);
            if (k0 | k1 | k2 | k3) {
                int c = (4 * v) % 25;
                int c1 = c + 1 == 25 ? 0 : c + 1;
                int c2 = c1 + 1 == 25 ? 0 : c1 + 1;
                int c3 = c2 + 1 == 25 ? 0 : c2 + 1;
                if (k0) { od.x = sqrtf(dv.x); oc.x = sctf[c];  om.x = 1.f; }
                if (k1) { od.y = sqrtf(dv.y); oc.y = sctf[c1]; om.y = 1.f; }
                if (k2) { od.z = sqrtf(dv.z); oc.z = sctf[c2]; om.z = 1.f; }
                if (k3) { od.w = sqrtf(dv.w); oc.w = sctf[c3]; om.w = 1.f; }
            }
            o0[v] = od;
            o1[v] = oc;
            o2[v] = om;
        }
    }
    __syncthreads();                    // order bulk stores before fixup

    // ---- tie fixup: re-write kept boundary candidates (incl. the 32nd) ----
#pragma unroll
    for (int u = 0; u < 2; u++) {
        if (s_total[u] > 32) {
            int n = min(s_n[u], CAP);
            if (tid < n) {
                unsigned long long k = slist[u][tid];
                float d = __uint_as_float((unsigned)(k >> 12));
                int cand = (int)(k & 0xFFFu);
                if (d == s_Tf[u] && cand <= s_Tc[u]) {
                    const size_t base = (size_t)(b * N_ + i0 + u) * NC + cand;
                    out[base]                  = sqrtf(d);
                    out[(size_t)S_ + base]     = sctf[cand % 25];
                    out[(size_t)2 * S_ + base] = 1.0f;
                }
            }
        }
    }

    if (tid == 0) {
        float contrib = 0.0f;
#pragma unroll
        for (int u = 0; u < 2; u++)
            contrib += fell[u] ? (float)(s_total[u] < 32 ? s_total[u] : 32) : 32.0f;
        atomicAdd(&out[(size_t)3 * S_ + b], contrib);
    }
}

extern "C" void kernel_launch(void* const* d_in, const int* in_sizes, int n_in,
                              void* d_out, int out_size) {
    const float* pos;
    const float* cell;
    if (n_in >= 2 && in_sizes[0] == B_ * N_ * 3) {
        pos  = (const float*)d_in[0];
        cell = (const float*)d_in[1];
    } else {
        pos  = (const float*)d_in[1];
        cell = (const float*)d_in[0];
    }
    float* out = (float*)d_out;

    zero_counts_kernel<<<1, 32>>>(out);
    pbc_graph_kernel<<<B_ * N_ / 2, NT>>>(pos, cell, out);
}

// round 7
// speedup vs baseline: 1.2252x; 1.2252x over previous
#include <cuda_runtime.h>
#include <math_constants.h>

#define B_    32
#define N_    128
#define C_    25
#define NC    3200                      // N_*C_ candidates per center
#define S_    13107200                  // B_*N_*N_*C_ elements per output tensor
#define RAD2  64.0f
#define EPS2  1e-4f
#define NT    256
#define NBIN  256
#define CAP   128
#define PREF  8.0f                      // prefilter bound for fine histogram

__device__ int g_epoch[B_];             // monotone; replay-safe modulo detection
__device__ int g_totals[B_ * N_];       // per-center clamped neighbor counts

__global__ __launch_bounds__(NT, 7)
void pbc_graph_kernel(const float* __restrict__ pos,
                      const float* __restrict__ cell,
                      float* __restrict__ out) {
    const int center = blockIdx.x;      // b*128 + i
    const int b = center >> 7;
    const int i = center & 127;
    const int tid = threadIdx.x;

    __shared__ float4 spos4[N_];
    __shared__ float4 soff[C_];
    __shared__ __align__(16) float sdist[NC];   // d2 or +inf
    __shared__ float  sctf[C_];
    __shared__ int    hist[NBIN];
    __shared__ int    s_n, s_t, s_cntlo, s_total;
    __shared__ unsigned long long slist[CAP];
    __shared__ float  s_Tf;
    __shared__ int    s_Tc;
    __shared__ int    s_last;
    __shared__ int    sred[8];

    // ---- setup ----
    if (tid < N_) {
        const float* p = pos + (size_t)b * N_ * 3 + tid * 3;
        spos4[tid] = make_float4(p[0], p[1], p[2], 0.0f);
    }
    if (tid >= N_ && tid < N_ + C_) {
        int c = tid - N_;
        float u0 = (float)(c / 5 - 2);
        float u1 = (float)(c % 5 - 2);
        const float* cb = cell + b * 9;
        soff[c] = make_float4(
            __fmaf_rn(u0, cb[0], __fmul_rn(u1, cb[3])),
            __fmaf_rn(u0, cb[1], __fmul_rn(u1, cb[4])),
            __fmaf_rn(u0, cb[2], __fmul_rn(u1, cb[5])), 0.0f);
        sctf[c] = (float)(5 * (c / 5 + c % 5));
    }
    hist[tid] = 0;
    if (tid == 0) { s_n = 0; s_t = -1; s_cntlo = 0; }
    __syncthreads();

    const float4 pi = spos4[i];

    // ---- phase 1: thread = (j, half); fully unrolled; fine histogram d2<8 ----
    const int j    = tid >> 1;
    const int half = tid & 1;
    const int cbeg = half ? 13 : 0;
    const int nits = 13 - half;          // 13 or 12
    const int jbase = j * 25;
    {
        const float4 rj = spos4[j];
        const float rx = __fsub_rn(rj.x, pi.x);
        const float ry = __fsub_rn(rj.y, pi.y);
        const float rz = __fsub_rn(rj.z, pi.z);
#pragma unroll
        for (int t = 0; t < 13; t++) {
            if (t < nits) {
                const int c = cbeg + t;
                float4 o = soff[c];
                float dx = __fadd_rn(rx, o.x);
                float dy = __fadd_rn(ry, o.y);
                float dz = __fadd_rn(rz, o.z);
                float d2 = __fmaf_rn(dx, dx, __fmaf_rn(dy, dy, __fmul_rn(dz, dz)));
                bool within = (d2 <= RAD2) && (d2 > EPS2);
                sdist[jbase + c] = within ? d2 : CUDART_INF_F;
                if (within && d2 < PREF)
                    atomicAdd(&hist[(int)(d2 * 32.0f)], 1);
            }
        }
    }

    // ---- phase 2: warp-0 scan; rare full-range fallback ----
    float scale = 32.0f;
    float bound = PREF;
    bool  fell  = false;
    for (int pass = 0; ; pass++) {
        __syncthreads();                 // hist ready
        if (tid < 32) {
            int loc[8], sum = 0;
#pragma unroll
            for (int k = 0; k < 8; k++) { loc[k] = hist[tid * 8 + k]; sum += loc[k]; }
            int pre = sum;
#pragma unroll
            for (int d = 1; d < 32; d <<= 1) {
                int v = __shfl_up_sync(0xffffffffu, pre, d);
                if (tid >= d) pre += v;
            }
            int total = __shfl_sync(0xffffffffu, pre, 31);
            pre -= sum;
            if (tid == 0) s_total = total;
            if (total > 32 && pre < 32 && 32 <= pre + sum) {
                int cum = pre;
#pragma unroll
                for (int k = 0; k < 8; k++) {
                    if (cum < 32 && cum + loc[k] >= 32) { s_t = tid * 8 + k; s_cntlo = cum; }
                    cum += loc[k];
                }
            }
        }
        __syncthreads();
        if (s_total >= 32 || pass == 1) break;
        // fallback: rebuild over full range (rare)
        hist[tid] = 0;
        __syncthreads();
        scale = 4.0f; bound = CUDART_INF_F; fell = true;
        for (int t = 0; t < nits; t++) {
            float d = sdist[jbase + cbeg + t];
            if (d <= RAD2)
                atomicAdd(&hist[min((int)(d * 4.0f), NBIN - 1)], 1);
        }
    }

    const int total = s_total;
    if (total > 32) {
        // compact boundary bin (unrolled), exact rank with stable (d2,cand) key
        const int tbin = s_t;
#pragma unroll
        for (int t = 0; t < 13; t++) {
            if (t < nits) {
                const int c = cbeg + t;
                float d = sdist[jbase + c];
                if (d < bound && min((int)(d * scale), NBIN - 1) == tbin) {
                    int p = atomicAdd(&s_n, 1);
                    if (p < CAP)
                        slist[p] = ((unsigned long long)__float_as_uint(d) << 12)
                                 | (unsigned)(jbase + c);
                }
            }
        }
        __syncthreads();
        int n = min(s_n, CAP);
        int need = 32 - s_cntlo;
        if (tid < n) {
            unsigned long long k = slist[tid];
            int r = 0;
            for (int m = 0; m < n; m++) r += (slist[m] < k) ? 1 : 0;
            if (r == need - 1) {
                s_Tf = __uint_as_float((unsigned)(k >> 12));
                s_Tc = (int)(k & 0xFFFu);
            }
        }
        __syncthreads();
    } else {
        if (tid == 0) { s_Tf = bound; s_Tc = -1; }  // keep all hist-covered
        __syncthreads();
    }

    const float Tf = s_Tf;

    // ---- phase 3: strict d < Tf bulk writes, fully unrolled ----
    const float4* sd4 = (const float4*)sdist;
    float4* o0 = (float4*)out                    + ((size_t)center * NC >> 2);
    float4* o1 = (float4*)(out + (size_t)S_)     + ((size_t)center * NC >> 2);
    float4* o2 = (float4*)(out + (size_t)2 * S_) + ((size_t)center * NC >> 2);

    auto write_group = [&](int v, int c) {
        float4 dv = sd4[v];
        bool k0 = dv.x < Tf, k1 = dv.y < Tf, k2 = dv.z < Tf, k3 = dv.w < Tf;
        float4 od = make_float4(0.f, 0.f, 0.f, 0.f);
        float4 oc = make_float4(0.f, 0.f, 0.f, 0.f);
        float4 om = make_float4(0.f, 0.f, 0.f, 0.f);
        if (k0 | k1 | k2 | k3) {          // rare
            int c1 = c  + 1 == 25 ? 0 : c  + 1;
            int c2 = c1 + 1 == 25 ? 0 : c1 + 1;
            int c3 = c2 + 1 == 25 ? 0 : c2 + 1;
            if (k0) { od.x = sqrtf(dv.x); oc.x = sctf[c];  om.x = 1.f; }
            if (k1) { od.y = sqrtf(dv.y); oc.y = sctf[c1]; om.y = 1.f; }
            if (k2) { od.z = sqrtf(dv.z); oc.z = sctf[c2]; om.z = 1.f; }
            if (k3) { od.w = sqrtf(dv.w); oc.w = sctf[c3]; om.w = 1.f; }
        }
        o0[v] = od; o1[v] = oc; o2[v] = om;
    };

    {
        int c0 = (4 * tid) % 25;
        int c = c0;
#pragma unroll
        for (int k = 0; k < 3; k++) {     // v = tid, tid+256, tid+512 (< 800)
            write_group(tid + 256 * k, c);
            c = (c == 0) ? 24 : c - 1;    // stride 1024 ≡ -1 (mod 25)
        }
        if (tid < 32) {                   // tail groups 768..799
            int ct = c0 + 22; if (ct >= 25) ct -= 25;
            write_group(768 + tid, ct);
        }
    }
    __syncthreads();                      // order bulk stores before fixup

    // ---- tie fixup: kept boundary candidates with d == Tf (incl. the 32nd) ----
    if (total > 32) {
        int n = min(s_n, CAP);
        if (tid < n) {
            unsigned long long k = slist[tid];
            float d = __uint_as_float((unsigned)(k >> 12));
            int cand = (int)(k & 0xFFFu);
            if (d == s_Tf && cand <= s_Tc) {
                const size_t base = (size_t)center * NC + cand;
                out[base]                  = sqrtf(d);
                out[(size_t)S_ + base]     = sctf[cand % 25];
                out[(size_t)2 * S_ + base] = 1.0f;
            }
        }
    }

    // ---- per-image counts: last block of image b reduces & writes (no zero kernel) ----
    if (tid == 0) {
        g_totals[center] = min(total, 32);
        __threadfence();
        int old = atomicAdd(&g_epoch[b], 1);
        s_last = ((old & (N_ - 1)) == (N_ - 1)) ? 1 : 0;
    }
    __syncthreads();
    if (s_last) {
        __threadfence();
        int v = (tid < N_) ? g_totals[b * N_ + tid] : 0;
        v = __reduce_add_sync(0xffffffffu, v);
        if ((tid & 31) == 0) sred[tid >> 5] = v;
        __syncthreads();
        if (tid == 0) {
            int s = 0;
#pragma unroll
            for (int q = 0; q < 8; q++) s += sred[q];
            out[(size_t)3 * S_ + b] = (float)s;
        }
    }
}

extern "C" void kernel_launch(void* const* d_in, const int* in_sizes, int n_in,
                              void* d_out, int out_size) {
    const float* pos;
    const float* cell;
    if (n_in >= 2 && in_sizes[0] == B_ * N_ * 3) {
        pos  = (const float*)d_in[0];
        cell = (const float*)d_in[1];
    } else {
        pos  = (const float*)d_in[1];
        cell = (const float*)d_in[0];
    }
    float* out = (float*)d_out;

    pbc_graph_kernel<<<B_ * N_, NT>>>(pos, cell, out);
}